// round 12
// baseline (speedup 1.0000x reference)
#include <cuda_runtime.h>
#include <cuda_bf16.h>
#include <cstdint>

#define N_NODES 50000
#define N_EDGES 800000
#define D 128
#define NL 3
#define BN_EPSF 1e-5f

// ---------------- scratch (device globals; no allocs allowed) ----------------
__device__ __align__(16) float g_x[N_NODES * D];
__device__ __align__(16) float g_h[N_NODES * D];
__device__ __align__(16) int   g_off[N_NODES + 4];
__device__ __align__(16) int   g_cur[N_NODES];
__device__ __align__(16) int   g_srcs[N_EDGES];
__device__ __align__(16) float g_ws[N_EDGES];
__device__ __align__(16) float g_stats[NL * 2 * D];   // per-layer [sum|sumsq]
__device__ __align__(16) int   g_bsum[64];
__device__ __align__(16) __nv_bfloat16 g_whi[NL * 2 * D * D];  // W^T split hi
__device__ __align__(16) __nv_bfloat16 g_wlo[NL * 2 * D * D];  // W^T split lo
__device__ int g_is32;

// ---------------- edge_index dtype sniff ----------------
__global__ void k_detect(const long long* __restrict__ ei) {
    if (threadIdx.x == 0 && blockIdx.x == 0) {
        int is32 = 0;
        for (int i = 0; i < 64; i++) {
            long long v = ei[i];
            if (v < 0 || v >= N_NODES) { is32 = 1; break; }
        }
        g_is32 = is32;
    }
}

// ---------------- weight pre-split: W[k][n] -> hi/lo[n*128+k] (transposed) ----
__global__ void k_wsplit(const float* __restrict__ W1, const float* __restrict__ W2) {
    int b = blockIdx.x;            // 0..5 = layer*2 + mat
    int l = b >> 1, m = b & 1;
    const float* W = (m ? W2 : W1) + l * D * D;
    __nv_bfloat16* hi = g_whi + b * D * D;
    __nv_bfloat16* lo = g_wlo + b * D * D;
    for (int idx = threadIdx.x; idx < D * D; idx += 256) {
        int k = idx >> 7, n = idx & 127;
        float w = W[idx];
        __nv_bfloat16 h = __float2bfloat16(w);
        __nv_bfloat16 lw = __float2bfloat16(w - __bfloat162float(h));
        hi[n * D + k] = h;
        lo[n * D + k] = lw;
    }
}

// ---------------- CSR build ----------------
__global__ void k_zero_cur() {
    int i = blockIdx.x * blockDim.x + threadIdx.x;
    if (i < N_NODES) g_cur[i] = 0;
    if (blockIdx.x == 0) {   // zero all per-layer BN stats once per launch
        for (int s = threadIdx.x; s < NL * 2 * D; s += 256) g_stats[s] = 0.f;
    }
}

__global__ void k_hist(const void* __restrict__ eiraw) {
    int e = blockIdx.x * blockDim.x + threadIdx.x;
    if (e >= N_EDGES) return;
    int dst = g_is32 ? ((const int*)eiraw)[N_EDGES + e]
                     : (int)((const long long*)eiraw)[N_EDGES + e];
    if ((unsigned)dst < N_NODES) atomicAdd(&g_cur[dst], 1);
}

__global__ void k_scan1() {
    __shared__ int s[1024];
    int b = blockIdx.x, tid = threadIdx.x;
    int i = b * 1024 + tid;
    int v = (i < N_NODES) ? g_cur[i] : 0;
    s[tid] = v;
    __syncthreads();
    for (int d = 1; d < 1024; d <<= 1) {
        int t = (tid >= d) ? s[tid - d] : 0;
        __syncthreads();
        s[tid] += t;
        __syncthreads();
    }
    if (i < N_NODES) g_off[i] = s[tid] - v;
    if (tid == 1023) g_bsum[b] = s[1023];
}

__global__ void k_scan2() {
    int acc = 0;
    for (int b = 0; b < 49; b++) { int v = g_bsum[b]; g_bsum[b] = acc; acc += v; }
    g_off[N_NODES] = acc;
}

__global__ void k_scan3() {
    int i = blockIdx.x * 1024 + threadIdx.x;
    if (i < N_NODES) {
        int o = g_off[i] + g_bsum[i >> 10];
        g_off[i] = o;
        g_cur[i] = o;
    }
}

__global__ void k_scatter(const void* __restrict__ eiraw, const float* __restrict__ ew) {
    int e = blockIdx.x * blockDim.x + threadIdx.x;
    if (e >= N_EDGES) return;
    int src, dst;
    if (g_is32) {
        const int* p = (const int*)eiraw;
        src = p[e]; dst = p[N_EDGES + e];
    } else {
        const long long* p = (const long long*)eiraw;
        src = (int)p[e]; dst = (int)p[N_EDGES + e];
    }
    if ((unsigned)src >= N_NODES || (unsigned)dst >= N_NODES) return;
    int q = atomicAdd(&g_cur[dst], 1);
    g_srcs[q] = src;
    g_ws[q] = ew[e];
}

// ---------------- fused agg + MLP: 64-row tiles, 2 CTAs/SM ----------------
// Phase 0: gather-aggregate this tile's rows straight from CSR into smem A
// (no g_agg round-trip). Then split-bf16 HMMA MLP as before.
#define TM 64
#define SROW 136
#define OFF_AH 0
#define OFF_AL 17408
#define OFF_BH 34816
#define OFF_BL 69632
#define SMEM_TOT 104448

__device__ __forceinline__ void mma16816(float* d, const uint32_t* a,
                                         uint32_t b0, uint32_t b1) {
    asm volatile(
        "mma.sync.aligned.m16n8k16.row.col.f32.bf16.bf16.f32 "
        "{%0,%1,%2,%3}, {%4,%5,%6,%7}, {%8,%9}, {%0,%1,%2,%3};"
        : "+f"(d[0]), "+f"(d[1]), "+f"(d[2]), "+f"(d[3])
        : "r"(a[0]), "r"(a[1]), "r"(a[2]), "r"(a[3]), "r"(b0), "r"(b1));
}

__device__ __forceinline__ void split2(float v0, float v1, uint32_t& hi, uint32_t& lo) {
    __nv_bfloat16 h0 = __float2bfloat16(v0);
    __nv_bfloat16 h1 = __float2bfloat16(v1);
    __nv_bfloat16 l0 = __float2bfloat16(v0 - __bfloat162float(h0));
    __nv_bfloat16 l1 = __float2bfloat16(v1 - __bfloat162float(h1));
    hi = (uint32_t)*(uint16_t*)&h0 | ((uint32_t)*(uint16_t*)&h1 << 16);
    lo = (uint32_t)*(uint16_t*)&l0 | ((uint32_t)*(uint16_t*)&l1 << 16);
}

// 64x128x128 GEMM (3 split passes) into d[2][4][4]; warp tile 32x32
__device__ __forceinline__ void gemm_mma(const char* sm, float d[2][4][4],
                                         int rbase, int cbase, int lane) {
    int gr = lane >> 2;
    int tg = (lane & 3) * 2;
#pragma unroll
    for (int pass = 0; pass < 3; pass++) {
        const uint16_t* A = (const uint16_t*)(sm + ((pass == 2) ? OFF_AL : OFF_AH));
        const uint16_t* B = (const uint16_t*)(sm + ((pass == 1) ? OFF_BL : OFF_BH));
#pragma unroll
        for (int k0 = 0; k0 < 8; k0++) {
            int kc = k0 * 16;
            uint32_t a[2][4];
#pragma unroll
            for (int mf = 0; mf < 2; mf++) {
                int r0 = rbase + mf * 16 + gr;
                a[mf][0] = *(const uint32_t*)&A[r0 * SROW + kc + tg];
                a[mf][1] = *(const uint32_t*)&A[(r0 + 8) * SROW + kc + tg];
                a[mf][2] = *(const uint32_t*)&A[r0 * SROW + kc + tg + 8];
                a[mf][3] = *(const uint32_t*)&A[(r0 + 8) * SROW + kc + tg + 8];
            }
#pragma unroll
            for (int nf = 0; nf < 4; nf++) {
                int n0 = cbase + nf * 8 + gr;
                uint32_t b0 = *(const uint32_t*)&B[n0 * SROW + kc + tg];
                uint32_t b1 = *(const uint32_t*)&B[n0 * SROW + kc + tg + 8];
                mma16816(d[0][nf], a[0], b0, b1);
                mma16816(d[1][nf], a[1], b0, b1);
            }
        }
    }
}

__global__ __launch_bounds__(256, 2) void k_fused(
    const float* __restrict__ xin,
    const float* __restrict__ b1, const float* __restrict__ b2,
    const float* __restrict__ epsv, int layer) {
    extern __shared__ char sm[];
    int tid = threadIdx.x, lane = tid & 31, wid = tid >> 5;
    int m0 = blockIdx.x * TM;
    int wm = wid >> 2, wn = wid & 3;          // 2 x 4 warp grid
    int rbase = wm * 32, cbase = wn * 32;
    int gr = lane >> 2, tg = (lane & 3) * 2;

    uint16_t* sAh = (uint16_t*)(sm + OFF_AH);
    uint16_t* sAl = (uint16_t*)(sm + OFF_AL);
    uint16_t* sBh = (uint16_t*)(sm + OFF_BH);
    uint16_t* sBl = (uint16_t*)(sm + OFF_BL);

    // ---- phase 0: gather-aggregate + (1+eps)*x -> split into sA ----
    // 8 warps x 8 rows each; per row: one warp, 8 gathers in flight.
    float e1 = 1.0f + epsv[layer];
    const float4* xr = (const float4*)xin;
#pragma unroll 1
    for (int rr = 0; rr < TM / 8; rr++) {
        int r = wid * (TM / 8) + rr;
        int node = m0 + r;
        float4 acc = make_float4(0.f, 0.f, 0.f, 0.f);
        if (node < N_NODES) {
            int beg = g_off[node];
            int end = g_off[node + 1];
            int j = beg;
            for (; j + 8 <= end; j += 8) {
                int   s[8];
                float w[8];
#pragma unroll
                for (int u = 0; u < 8; u++) { s[u] = g_srcs[j + u]; w[u] = g_ws[j + u]; }
                float4 v[8];
#pragma unroll
                for (int u = 0; u < 8; u++) v[u] = xr[s[u] * (D / 4) + lane];
#pragma unroll
                for (int u = 0; u < 8; u++) {
                    acc.x += w[u] * v[u].x;
                    acc.y += w[u] * v[u].y;
                    acc.z += w[u] * v[u].z;
                    acc.w += w[u] * v[u].w;
                }
            }
            for (; j + 2 <= end; j += 2) {
                int s0 = g_srcs[j];     float w0 = g_ws[j];
                int s1 = g_srcs[j + 1]; float w1 = g_ws[j + 1];
                float4 v0 = xr[s0 * (D / 4) + lane];
                float4 v1 = xr[s1 * (D / 4) + lane];
                acc.x += w0 * v0.x + w1 * v1.x;
                acc.y += w0 * v0.y + w1 * v1.y;
                acc.z += w0 * v0.z + w1 * v1.z;
                acc.w += w0 * v0.w + w1 * v1.w;
            }
            if (j < end) {
                int s0 = g_srcs[j]; float w0 = g_ws[j];
                float4 v0 = xr[s0 * (D / 4) + lane];
                acc.x += w0 * v0.x; acc.y += w0 * v0.y;
                acc.z += w0 * v0.z; acc.w += w0 * v0.w;
            }
            float4 xv = xr[node * (D / 4) + lane];
            acc.x += e1 * xv.x; acc.y += e1 * xv.y;
            acc.z += e1 * xv.z; acc.w += e1 * xv.w;
        }
        int c = lane * 4;
        uint32_t h0, l0, h1, l1;
        split2(acc.x, acc.y, h0, l0);
        split2(acc.z, acc.w, h1, l1);
        *(uint32_t*)&sAh[r * SROW + c]     = h0;
        *(uint32_t*)&sAl[r * SROW + c]     = l0;
        *(uint32_t*)&sAh[r * SROW + c + 2] = h1;
        *(uint32_t*)&sAl[r * SROW + c + 2] = l1;
    }
    // ---- stage pre-split W1^T (pure copy) ----
    {
        const __nv_bfloat16* hi = g_whi + (layer * 2 + 0) * D * D;
        const __nv_bfloat16* lo = g_wlo + (layer * 2 + 0) * D * D;
        for (int idx = tid * 8; idx < D * D; idx += 2048) {
            int n = idx >> 7, k = idx & 127;
            *(uint4*)&sBh[n * SROW + k] = *(const uint4*)&hi[idx];
            *(uint4*)&sBl[n * SROW + k] = *(const uint4*)&lo[idx];
        }
    }
    __syncthreads();

    // ---- GEMM1: H1 = A @ W1 ----
    float d[2][4][4];
#pragma unroll
    for (int mf = 0; mf < 2; mf++)
#pragma unroll
        for (int nf = 0; nf < 4; nf++)
#pragma unroll
            for (int q = 0; q < 4; q++) d[mf][nf][q] = 0.f;
    gemm_mma(sm, d, rbase, cbase, lane);
    __syncthreads();

    // ---- epilogue1: relu(H1 + b1) -> split back into sA ----
    {
        const float* bb = b1 + layer * D;
#pragma unroll
        for (int mf = 0; mf < 2; mf++) {
            int r0 = rbase + mf * 16 + gr;
#pragma unroll
            for (int nf = 0; nf < 4; nf++) {
                int col = cbase + nf * 8 + tg;
                float bv0 = bb[col], bv1 = bb[col + 1];
                float v00 = fmaxf(d[mf][nf][0] + bv0, 0.f);
                float v01 = fmaxf(d[mf][nf][1] + bv1, 0.f);
                float v10 = fmaxf(d[mf][nf][2] + bv0, 0.f);
                float v11 = fmaxf(d[mf][nf][3] + bv1, 0.f);
                uint32_t h, l;
                split2(v00, v01, h, l);
                *(uint32_t*)&sAh[r0 * SROW + col] = h;
                *(uint32_t*)&sAl[r0 * SROW + col] = l;
                split2(v10, v11, h, l);
                *(uint32_t*)&sAh[(r0 + 8) * SROW + col] = h;
                *(uint32_t*)&sAl[(r0 + 8) * SROW + col] = l;
            }
        }
    }
    // ---- stage pre-split W2^T ----
    {
        const __nv_bfloat16* hi = g_whi + (layer * 2 + 1) * D * D;
        const __nv_bfloat16* lo = g_wlo + (layer * 2 + 1) * D * D;
        for (int idx = tid * 8; idx < D * D; idx += 2048) {
            int n = idx >> 7, k = idx & 127;
            *(uint4*)&sBh[n * SROW + k] = *(const uint4*)&hi[idx];
            *(uint4*)&sBl[n * SROW + k] = *(const uint4*)&lo[idx];
        }
    }
    __syncthreads();

    // ---- GEMM2: H2 = relu(H1) @ W2 ----
#pragma unroll
    for (int mf = 0; mf < 2; mf++)
#pragma unroll
        for (int nf = 0; nf < 4; nf++)
#pragma unroll
            for (int q = 0; q < 4; q++) d[mf][nf][q] = 0.f;
    gemm_mma(sm, d, rbase, cbase, lane);
    __syncthreads();

    // ---- epilogue2: h = H2 + b2 -> sT (zero OOB rows) ----
    float* sT = (float*)(sm + OFF_BH);   // 64 x 129 floats = 33024B (aliases sB)
    {
        const float* bb = b2 + layer * D;
#pragma unroll
        for (int mf = 0; mf < 2; mf++) {
            int r0 = rbase + mf * 16 + gr;
            bool v0ok = (m0 + r0) < N_NODES;
            bool v1ok = (m0 + r0 + 8) < N_NODES;
#pragma unroll
            for (int nf = 0; nf < 4; nf++) {
                int col = cbase + nf * 8 + tg;
                float bv0 = bb[col], bv1 = bb[col + 1];
                sT[r0 * 129 + col]           = v0ok ? d[mf][nf][0] + bv0 : 0.f;
                sT[r0 * 129 + col + 1]       = v0ok ? d[mf][nf][1] + bv1 : 0.f;
                sT[(r0 + 8) * 129 + col]     = v1ok ? d[mf][nf][2] + bv0 : 0.f;
                sT[(r0 + 8) * 129 + col + 1] = v1ok ? d[mf][nf][3] + bv1 : 0.f;
            }
        }
    }
    __syncthreads();

    // ---- BN column partial sums: 2 row-halves per column across 256 threads ----
    float* sRedS = (float*)(sm + OFF_AL);        // 256 floats
    float* sRedQ = (float*)(sm + OFF_AL) + 256;  // 256 floats
    {
        int col = tid & 127, rq = tid >> 7;      // rq in {0,1}
        float s = 0.f, q = 0.f;
        int rlo = rq * 32;
#pragma unroll 4
        for (int r = rlo; r < rlo + 32; r++) {
            float h = sT[r * 129 + col];
            s += h; q += h * h;
        }
        sRedS[rq * 128 + col] = s;
        sRedQ[rq * 128 + col] = q;
    }
    __syncthreads();
    float* stats = g_stats + layer * 2 * D;
    if (tid < 128) {
        atomicAdd(&stats[tid], sRedS[tid] + sRedS[128 + tid]);
    } else {
        int c = tid - 128;
        atomicAdd(&stats[128 + c], sRedQ[c] + sRedQ[128 + c]);
    }
    // ---- coalesced g_h store ----
    for (int idx = tid; idx < TM * 32; idx += 256) {
        int r = idx >> 5, c4 = (idx & 31) << 2;
        int gro = m0 + r;
        if (gro < N_NODES) {
            float4 o = make_float4(sT[r * 129 + c4], sT[r * 129 + c4 + 1],
                                   sT[r * 129 + c4 + 2], sT[r * 129 + c4 + 3]);
            *(float4*)(g_h + gro * D + c4) = o;
        }
    }
}

// ---------------- BN apply + relu + residual ----------------
__global__ void k_bn(const float* __restrict__ xin, float* __restrict__ xout,
                     const float* __restrict__ gamma, const float* __restrict__ beta,
                     int layer) {
    int idx = blockIdx.x * blockDim.x + threadIdx.x;
    if (idx >= N_NODES * D / 4) return;
    int c = (idx & 31) * 4;
    const float* stats = g_stats + layer * 2 * D;
    float4 s  = *(const float4*)(stats + c);
    float4 sq = *(const float4*)(stats + D + c);
    float4 g  = *(const float4*)(gamma + layer * D + c);
    float4 be = *(const float4*)(beta + layer * D + c);
    float4 h  = ((const float4*)g_h)[idx];
    float4 xv = ((const float4*)xin)[idx];
    const float inv = 1.0f / (float)N_NODES;
    float4 o;
    { float mu = s.x * inv, var = sq.x * inv - mu * mu, r = rsqrtf(var + BN_EPSF);
      o.x = xv.x + fmaxf(g.x * (h.x - mu) * r + be.x, 0.f); }
    { float mu = s.y * inv, var = sq.y * inv - mu * mu, r = rsqrtf(var + BN_EPSF);
      o.y = xv.y + fmaxf(g.y * (h.y - mu) * r + be.y, 0.f); }
    { float mu = s.z * inv, var = sq.z * inv - mu * mu, r = rsqrtf(var + BN_EPSF);
      o.z = xv.z + fmaxf(g.z * (h.z - mu) * r + be.z, 0.f); }
    { float mu = s.w * inv, var = sq.w * inv - mu * mu, r = rsqrtf(var + BN_EPSF);
      o.w = xv.w + fmaxf(g.w * (h.w - mu) * r + be.w, 0.f); }
    ((float4*)xout)[idx] = o;
}

// ---------------- launch ----------------
extern "C" void kernel_launch(void* const* d_in, const int* in_sizes, int n_in,
                              void* d_out, int out_size) {
    const float* x     = (const float*)d_in[0];
    const void*  eiraw = d_in[1];
    const float* ew    = (const float*)d_in[3];
    const float* W1    = (const float*)d_in[4];
    const float* b1    = (const float*)d_in[5];
    const float* W2    = (const float*)d_in[6];
    const float* b2    = (const float*)d_in[7];
    const float* eps   = (const float*)d_in[8];
    const float* gamma = (const float*)d_in[9];
    const float* beta  = (const float*)d_in[10];
    float* out = (float*)d_out;

    cudaFuncSetAttribute(k_fused, cudaFuncAttributeMaxDynamicSharedMemorySize, SMEM_TOT);

    float* gx = nullptr;
    cudaGetSymbolAddress((void**)&gx, g_x);

    k_detect<<<1, 32>>>((const long long*)eiraw);
    k_wsplit<<<6, 256>>>(W1, W2);
    k_zero_cur<<<(N_NODES + 255) / 256, 256>>>();
    k_hist<<<(N_EDGES + 255) / 256, 256>>>(eiraw);
    k_scan1<<<49, 1024>>>();
    k_scan2<<<1, 1>>>();
    k_scan3<<<49, 1024>>>();
    k_scatter<<<(N_EDGES + 255) / 256, 256>>>(eiraw, ew);

    const int n_blk = (N_NODES + TM - 1) / TM;
    const float* xin = x;
    for (int l = 0; l < NL; l++) {
        k_fused<<<n_blk, 256, SMEM_TOT>>>(xin, b1, b2, eps, l);
        float* xout = (l == NL - 1) ? out : gx;
        k_bn<<<(N_NODES * D / 4 + 255) / 256, 256>>>(xin, xout, gamma, beta, l);
        xin = xout;
    }
}

// round 13
// speedup vs baseline: 1.3054x; 1.3054x over previous
#include <cuda_runtime.h>
#include <cuda_bf16.h>
#include <cstdint>

#define N_NODES 50000
#define N_EDGES 800000
#define D 128
#define NL 3
#define BN_EPSF 1e-5f

// ---------------- scratch (device globals; no allocs allowed) ----------------
__device__ __align__(16) float g_agg[N_NODES * D];
__device__ __align__(16) float g_x[N_NODES * D];
__device__ __align__(16) float g_h[N_NODES * D];
__device__ __align__(16) int   g_off[N_NODES + 4];
__device__ __align__(16) int   g_cur[N_NODES];
__device__ __align__(16) int   g_srcs[N_EDGES];
__device__ __align__(16) float g_ws[N_EDGES];
__device__ __align__(16) float g_stats[NL * 2 * D];      // per-layer [sum|sumsq]
__device__ __align__(16) int   g_bsum[64];
__device__ __align__(16) float g_wt[NL * 2 * D * D];     // W^T, tf32-rounded fp32
__device__ int g_is32;

__device__ __forceinline__ uint32_t f2tf32(float v) {
    uint32_t r;
    asm("cvt.rna.tf32.f32 %0, %1;" : "=r"(r) : "f"(v));
    return r;
}

// ---------------- init: weight pre-round (tf32, transposed) + detect + zeros ----
__global__ void k_init(const float* __restrict__ W1, const float* __restrict__ W2,
                       const long long* __restrict__ ei) {
    int b = blockIdx.x, tid = threadIdx.x;
    if (b < 6) {                       // W^T tf32: wt[b][n][k] = rna(W[k][n])
        int l = b >> 1, m = b & 1;
        const float* W = (m ? W2 : W1) + l * D * D;
        float* wt = g_wt + b * D * D;
        for (int idx = tid; idx < D * D; idx += 256) {
            int k = idx >> 7, n = idx & 127;
            wt[n * D + k] = __uint_as_float(f2tf32(W[idx]));
        }
    } else if (b == 6) {               // dtype sniff + BN stats zero
        if (tid == 0) {
            int is32 = 0;
            for (int i = 0; i < 64; i++) {
                long long v = ei[i];
                if (v < 0 || v >= N_NODES) { is32 = 1; break; }
            }
            g_is32 = is32;
        }
        for (int s = tid; s < NL * 2 * D; s += 256) g_stats[s] = 0.f;
    } else {                           // zero degree counters
        int i = (b - 7) * 256 + tid;
        if (i < N_NODES) g_cur[i] = 0;
    }
}

// ---------------- CSR build ----------------
__global__ void k_hist(const void* __restrict__ eiraw) {
    int e = blockIdx.x * blockDim.x + threadIdx.x;
    if (e >= N_EDGES) return;
    int dst = g_is32 ? ((const int*)eiraw)[N_EDGES + e]
                     : (int)((const long long*)eiraw)[N_EDGES + e];
    if ((unsigned)dst < N_NODES) atomicAdd(&g_cur[dst], 1);
}

__global__ void k_scan1() {
    __shared__ int s[1024];
    int b = blockIdx.x, tid = threadIdx.x;
    int i = b * 1024 + tid;
    int v = (i < N_NODES) ? g_cur[i] : 0;
    s[tid] = v;
    __syncthreads();
    for (int d = 1; d < 1024; d <<= 1) {
        int t = (tid >= d) ? s[tid - d] : 0;
        __syncthreads();
        s[tid] += t;
        __syncthreads();
    }
    if (i < N_NODES) g_off[i] = s[tid] - v;   // block-local exclusive
    if (tid == 1023) g_bsum[b] = s[1023];
}

// fused cross-block prefix + fixup (each block sums its predecessors' bsums)
__global__ void k_scan3() {
    __shared__ int pre;
    if (threadIdx.x == 0) {
        int acc = 0;
        for (int b = 0; b < blockIdx.x; b++) acc += g_bsum[b];
        pre = acc;
        if (blockIdx.x == 48) g_off[N_NODES] = acc + g_bsum[48];
    }
    __syncthreads();
    int i = blockIdx.x * 1024 + threadIdx.x;
    if (i < N_NODES) {
        int o = g_off[i] + pre;
        g_off[i] = o;
        g_cur[i] = o;
    }
}

__global__ void k_scatter(const void* __restrict__ eiraw, const float* __restrict__ ew) {
    int e = blockIdx.x * blockDim.x + threadIdx.x;
    if (e >= N_EDGES) return;
    int src, dst;
    if (g_is32) {
        const int* p = (const int*)eiraw;
        src = p[e]; dst = p[N_EDGES + e];
    } else {
        const long long* p = (const long long*)eiraw;
        src = (int)p[e]; dst = (int)p[N_EDGES + e];
    }
    if ((unsigned)src >= N_NODES || (unsigned)dst >= N_NODES) return;
    int q = atomicAdd(&g_cur[dst], 1);
    g_srcs[q] = src;
    g_ws[q] = ew[e];
}

// ---------------- aggregation: one warp per node, 8 gathers in flight ----------
__global__ __launch_bounds__(256) void k_agg(const float* __restrict__ xin) {
    int warp = (blockIdx.x * blockDim.x + threadIdx.x) >> 5;
    int lane = threadIdx.x & 31;
    if (warp >= N_NODES) return;
    int beg = g_off[warp];
    int end = g_off[warp + 1];
    float4 acc = make_float4(0.f, 0.f, 0.f, 0.f);
    const float4* xr = (const float4*)xin;
    int j = beg;
    for (; j + 8 <= end; j += 8) {
        int   s[8];
        float w[8];
#pragma unroll
        for (int u = 0; u < 8; u++) { s[u] = g_srcs[j + u]; w[u] = g_ws[j + u]; }
        float4 v[8];
#pragma unroll
        for (int u = 0; u < 8; u++) v[u] = xr[s[u] * (D / 4) + lane];
#pragma unroll
        for (int u = 0; u < 8; u++) {
            acc.x += w[u] * v[u].x;
            acc.y += w[u] * v[u].y;
            acc.z += w[u] * v[u].z;
            acc.w += w[u] * v[u].w;
        }
    }
    for (; j + 2 <= end; j += 2) {
        int s0 = g_srcs[j];     float w0 = g_ws[j];
        int s1 = g_srcs[j + 1]; float w1 = g_ws[j + 1];
        float4 v0 = xr[s0 * (D / 4) + lane];
        float4 v1 = xr[s1 * (D / 4) + lane];
        acc.x += w0 * v0.x + w1 * v1.x;
        acc.y += w0 * v0.y + w1 * v1.y;
        acc.z += w0 * v0.z + w1 * v1.z;
        acc.w += w0 * v0.w + w1 * v1.w;
    }
    if (j < end) {
        int s0 = g_srcs[j]; float w0 = g_ws[j];
        float4 v0 = xr[s0 * (D / 4) + lane];
        acc.x += w0 * v0.x; acc.y += w0 * v0.y;
        acc.z += w0 * v0.z; acc.w += w0 * v0.w;
    }
    ((float4*)g_agg)[warp * (D / 4) + lane] = acc;
}

// ---------------- single-pass tf32 mma.sync fused MLP ----------------
// 512 threads, 4x4 warp grid (warp tile 32x32), 128-row tile.
// smem: sA [128][132] fp32 @ 0, sB [128][132] fp32 @ 67584.
// sT (128x129 f32) aliases sB; BN-reduce arrays alias sA.
#define SROW 132
#define OFF_A 0
#define OFF_B 67584
#define SMEM_TOT 135168

__device__ __forceinline__ void mma_tf32(float* d, const uint32_t* a,
                                         uint32_t b0, uint32_t b1) {
    asm volatile(
        "mma.sync.aligned.m16n8k8.row.col.f32.tf32.tf32.f32 "
        "{%0,%1,%2,%3}, {%4,%5,%6,%7}, {%8,%9}, {%0,%1,%2,%3};"
        : "+f"(d[0]), "+f"(d[1]), "+f"(d[2]), "+f"(d[3])
        : "r"(a[0]), "r"(a[1]), "r"(a[2]), "r"(a[3]), "r"(b0), "r"(b1));
}

// 128x128x128 GEMM, single tf32 pass, into d[2][4][4]; warp tile 32x32
__device__ __forceinline__ void gemm_tf32(const char* sm, float d[2][4][4],
                                          int rbase, int cbase, int lane) {
    int gr = lane >> 2;
    int tg = lane & 3;
    const uint32_t* A = (const uint32_t*)(sm + OFF_A);
    const uint32_t* B = (const uint32_t*)(sm + OFF_B);
#pragma unroll
    for (int k0 = 0; k0 < 16; k0++) {
        int kc = k0 * 8;
        uint32_t a[2][4];
#pragma unroll
        for (int mf = 0; mf < 2; mf++) {
            int r0 = rbase + mf * 16 + gr;
            a[mf][0] = A[r0 * SROW + kc + tg];
            a[mf][1] = A[(r0 + 8) * SROW + kc + tg];
            a[mf][2] = A[r0 * SROW + kc + tg + 4];
            a[mf][3] = A[(r0 + 8) * SROW + kc + tg + 4];
        }
#pragma unroll
        for (int nf = 0; nf < 4; nf++) {
            int n0 = cbase + nf * 8 + gr;
            uint32_t b0 = B[n0 * SROW + kc + tg];
            uint32_t b1 = B[n0 * SROW + kc + tg + 4];
            mma_tf32(d[0][nf], a[0], b0, b1);
            mma_tf32(d[1][nf], a[1], b0, b1);
        }
    }
}

__global__ __launch_bounds__(512, 1) void k_mlp(
    const float* __restrict__ xin,
    const float* __restrict__ b1, const float* __restrict__ b2,
    const float* __restrict__ epsv, int layer) {
    extern __shared__ char sm[];
    int tid = threadIdx.x, lane = tid & 31, wid = tid >> 5;
    int m0 = blockIdx.x * 128;
    int wm = wid >> 2, wn = wid & 3;          // 4 x 4 warp grid
    int rbase = wm * 32, cbase = wn * 32;
    int gr = lane >> 2, tg2 = (lane & 3) * 2;

    float* sA = (float*)(sm + OFF_A);
    float* sB = (float*)(sm + OFF_B);

    // ---- stage A = tf32((1+eps)*x + agg), zero OOB rows ----
    float e1 = 1.0f + epsv[layer];
    for (int idx = tid * 4; idx < D * D; idx += 2048) {
        int r = idx >> 7, c = idx & 127;
        int gro = m0 + r;
        float4 v = make_float4(0.f, 0.f, 0.f, 0.f);
        if (gro < N_NODES) {
            float4 xv = *(const float4*)(xin + gro * D + c);
            float4 av = *(const float4*)(g_agg + gro * D + c);
            v.x = e1 * xv.x + av.x; v.y = e1 * xv.y + av.y;
            v.z = e1 * xv.z + av.z; v.w = e1 * xv.w + av.w;
        }
        float4 t;
        t.x = __uint_as_float(f2tf32(v.x));
        t.y = __uint_as_float(f2tf32(v.y));
        t.z = __uint_as_float(f2tf32(v.z));
        t.w = __uint_as_float(f2tf32(v.w));
        *(float4*)&sA[r * SROW + c] = t;
    }
    // ---- stage W1^T (already tf32-rounded; pure copy) ----
    {
        const float* wt = g_wt + (layer * 2 + 0) * D * D;
        for (int idx = tid * 4; idx < D * D; idx += 2048) {
            int n = idx >> 7, k = idx & 127;
            *(float4*)&sB[n * SROW + k] = *(const float4*)&wt[idx];
        }
    }
    __syncthreads();

    // ---- GEMM1: H1 = A @ W1 ----
    float d[2][4][4];
#pragma unroll
    for (int mf = 0; mf < 2; mf++)
#pragma unroll
        for (int nf = 0; nf < 4; nf++)
#pragma unroll
            for (int q = 0; q < 4; q++) d[mf][nf][q] = 0.f;
    gemm_tf32(sm, d, rbase, cbase, lane);
    __syncthreads();

    // ---- epilogue1: tf32(relu(H1 + b1)) -> back into sA ----
    {
        const float* bb = b1 + layer * D;
#pragma unroll
        for (int mf = 0; mf < 2; mf++) {
            int r0 = rbase + mf * 16 + gr;
#pragma unroll
            for (int nf = 0; nf < 4; nf++) {
                int col = cbase + nf * 8 + tg2;
                float bv0 = bb[col], bv1 = bb[col + 1];
                sA[r0 * SROW + col]           = __uint_as_float(f2tf32(fmaxf(d[mf][nf][0] + bv0, 0.f)));
                sA[r0 * SROW + col + 1]       = __uint_as_float(f2tf32(fmaxf(d[mf][nf][1] + bv1, 0.f)));
                sA[(r0 + 8) * SROW + col]     = __uint_as_float(f2tf32(fmaxf(d[mf][nf][2] + bv0, 0.f)));
                sA[(r0 + 8) * SROW + col + 1] = __uint_as_float(f2tf32(fmaxf(d[mf][nf][3] + bv1, 0.f)));
            }
        }
    }
    // ---- stage W2^T ----
    {
        const float* wt = g_wt + (layer * 2 + 1) * D * D;
        for (int idx = tid * 4; idx < D * D; idx += 2048) {
            int n = idx >> 7, k = idx & 127;
            *(float4*)&sB[n * SROW + k] = *(const float4*)&wt[idx];
        }
    }
    __syncthreads();

    // ---- GEMM2: H2 = relu(H1) @ W2 ----
#pragma unroll
    for (int mf = 0; mf < 2; mf++)
#pragma unroll
        for (int nf = 0; nf < 4; nf++)
#pragma unroll
            for (int q = 0; q < 4; q++) d[mf][nf][q] = 0.f;
    gemm_tf32(sm, d, rbase, cbase, lane);
    __syncthreads();

    // ---- epilogue2: h = H2 + b2 -> sT (zero OOB rows) ----
    float* sT = (float*)(sm + OFF_B);   // 128 x 129 floats = 66048B <= 67584B
    {
        const float* bb = b2 + layer * D;
#pragma unroll
        for (int mf = 0; mf < 2; mf++) {
            int r0 = rbase + mf * 16 + gr;
            bool v0ok = (m0 + r0) < N_NODES;
            bool v1ok = (m0 + r0 + 8) < N_NODES;
#pragma unroll
            for (int nf = 0; nf < 4; nf++) {
                int col = cbase + nf * 8 + tg2;
                float bv0 = bb[col], bv1 = bb[col + 1];
                sT[r0 * 129 + col]           = v0ok ? d[mf][nf][0] + bv0 : 0.f;
                sT[r0 * 129 + col + 1]       = v0ok ? d[mf][nf][1] + bv1 : 0.f;
                sT[(r0 + 8) * 129 + col]     = v1ok ? d[mf][nf][2] + bv0 : 0.f;
                sT[(r0 + 8) * 129 + col + 1] = v1ok ? d[mf][nf][3] + bv1 : 0.f;
            }
        }
    }
    __syncthreads();

    // ---- BN column partial sums: 4 row-quarters per column (alias sA) ----
    float* sRedS = (float*)(sm + OFF_A);         // 512 floats
    float* sRedQ = (float*)(sm + OFF_A) + 512;   // 512 floats
    {
        int col = tid & 127, rq = tid >> 7;
        float s = 0.f, q = 0.f;
        int rlo = rq * 32;
#pragma unroll 4
        for (int r = rlo; r < rlo + 32; r++) {
            float h = sT[r * 129 + col];
            s += h; q += h * h;
        }
        sRedS[rq * 128 + col] = s;
        sRedQ[rq * 128 + col] = q;
    }
    __syncthreads();
    float* stats = g_stats + layer * 2 * D;
    if (tid < 128) {
        atomicAdd(&stats[tid],
                  sRedS[tid] + sRedS[128 + tid] + sRedS[256 + tid] + sRedS[384 + tid]);
    } else if (tid < 256) {
        int c = tid - 128;
        atomicAdd(&stats[128 + c],
                  sRedQ[c] + sRedQ[128 + c] + sRedQ[256 + c] + sRedQ[384 + c]);
    }
    // ---- coalesced g_h store ----
    for (int idx = tid; idx < 4096; idx += 512) {
        int r = idx >> 5, c4 = (idx & 31) << 2;
        int gro = m0 + r;
        if (gro < N_NODES) {
            float4 o = make_float4(sT[r * 129 + c4], sT[r * 129 + c4 + 1],
                                   sT[r * 129 + c4 + 2], sT[r * 129 + c4 + 3]);
            *(float4*)(g_h + gro * D + c4) = o;
        }
    }
}

// ---------------- BN apply + relu + residual ----------------
__global__ void k_bn(const float* __restrict__ xin, float* __restrict__ xout,
                     const float* __restrict__ gamma, const float* __restrict__ beta,
                     int layer) {
    int idx = blockIdx.x * blockDim.x + threadIdx.x;
    if (idx >= N_NODES * D / 4) return;
    int c = (idx & 31) * 4;
    const float* stats = g_stats + layer * 2 * D;
    float4 s  = *(const float4*)(stats + c);
    float4 sq = *(const float4*)(stats + D + c);
    float4 g  = *(const float4*)(gamma + layer * D + c);
    float4 be = *(const float4*)(beta + layer * D + c);
    float4 h  = ((const float4*)g_h)[idx];
    float4 xv = ((const float4*)xin)[idx];
    const float inv = 1.0f / (float)N_NODES;
    float4 o;
    { float mu = s.x * inv, var = sq.x * inv - mu * mu, r = rsqrtf(var + BN_EPSF);
      o.x = xv.x + fmaxf(g.x * (h.x - mu) * r + be.x, 0.f); }
    { float mu = s.y * inv, var = sq.y * inv - mu * mu, r = rsqrtf(var + BN_EPSF);
      o.y = xv.y + fmaxf(g.y * (h.y - mu) * r + be.y, 0.f); }
    { float mu = s.z * inv, var = sq.z * inv - mu * mu, r = rsqrtf(var + BN_EPSF);
      o.z = xv.z + fmaxf(g.z * (h.z - mu) * r + be.z, 0.f); }
    { float mu = s.w * inv, var = sq.w * inv - mu * mu, r = rsqrtf(var + BN_EPSF);
      o.w = xv.w + fmaxf(g.w * (h.w - mu) * r + be.w, 0.f); }
    ((float4*)xout)[idx] = o;
}

// ---------------- launch ----------------
extern "C" void kernel_launch(void* const* d_in, const int* in_sizes, int n_in,
                              void* d_out, int out_size) {
    const float* x     = (const float*)d_in[0];
    const void*  eiraw = d_in[1];
    const float* ew    = (const float*)d_in[3];
    const float* W1    = (const float*)d_in[4];
    const float* b1    = (const float*)d_in[5];
    const float* W2    = (const float*)d_in[6];
    const float* b2    = (const float*)d_in[7];
    const float* eps   = (const float*)d_in[8];
    const float* gamma = (const float*)d_in[9];
    const float* beta  = (const float*)d_in[10];
    float* out = (float*)d_out;

    cudaFuncSetAttribute(k_mlp, cudaFuncAttributeMaxDynamicSharedMemorySize, SMEM_TOT);

    float* gx = nullptr;
    cudaGetSymbolAddress((void**)&gx, g_x);

    k_init<<<7 + (N_NODES + 255) / 256, 256>>>(W1, W2, (const long long*)eiraw);
    k_hist<<<(N_EDGES + 255) / 256, 256>>>(eiraw);
    k_scan1<<<49, 1024>>>();
    k_scan3<<<49, 1024>>>();
    k_scatter<<<(N_EDGES + 255) / 256, 256>>>(eiraw, ew);

    const int n_mlp_blk = (N_NODES + 127) / 128;
    const float* xin = x;
    for (int l = 0; l < NL; l++) {
        k_agg<<<(N_NODES + 7) / 8, 256>>>(xin);
        k_mlp<<<n_mlp_blk, 512, SMEM_TOT>>>(xin, b1, b2, eps, l);
        float* xout = (l == NL - 1) ? out : gx;
        k_bn<<<(N_NODES * D / 4 + 255) / 256, 256>>>(xin, xout, gamma, beta, l);
        xin = xout;
    }
}